// round 4
// baseline (speedup 1.0000x reference)
#include <cuda_runtime.h>

#define LNUM 3
#define ENUM 1000000
#define NNODE 100000
#define DDIM 64
#define ADIM 8
#define NR2C 461
#define QNUM 1000
#define ENTC 10000

// ---------------- scratch (device globals; no allocation) ----------------
__device__ float g_state[NNODE * DDIM];
__device__ float g_agg[NNODE * DDIM];
__device__ float g_nproj[NNODE * ADIM];
__device__ float g_rproj[NR2C * ADIM];
__device__ float g_qproj[QNUM * ADIM];
__device__ float g_bWh[LNUM * 4096];    // per-layer 8ks x 8nt x 32 x 2
__device__ float g_bWih[12288];         // 8ks x 24nt x 32 x 2
__device__ float g_bWhh[12288];
__device__ float g_scores[NNODE];
__device__ int   g_winner[QNUM * ENTC];
// CSR scratch
__device__ int   g_cnt[LNUM * NNODE];
__device__ int   g_rs[LNUM * (NNODE + 1)];
__device__ int   g_rsw[LNUM * NNODE];
__device__ int4  g_epack[(size_t)LNUM * ENUM];

// ---------------- helpers ----------------
__device__ __forceinline__ unsigned f2tf(float x) {
    unsigned u;
    asm("cvt.rna.tf32.f32 %0, %1;" : "=r"(u) : "f"(x));
    return u;
}
__device__ __forceinline__ float tf(float x) { return __uint_as_float(f2tf(x)); }
__device__ __forceinline__ float sigf(float x) { return 1.f / (1.f + __expf(-x)); }

__device__ __forceinline__ void mma8(float acc[4], unsigned a0, unsigned a1,
                                     unsigned a2, unsigned a3, unsigned b0, unsigned b1) {
    asm volatile(
        "mma.sync.aligned.m16n8k8.row.col.f32.tf32.tf32.f32 "
        "{%0,%1,%2,%3}, {%4,%5,%6,%7}, {%8,%9}, {%0,%1,%2,%3};"
        : "+f"(acc[0]), "+f"(acc[1]), "+f"(acc[2]), "+f"(acc[3])
        : "r"(a0), "r"(a1), "r"(a2), "r"(a3), "r"(b0), "r"(b1));
}

// ---------------- init kernels ----------------
__global__ void k_zero4(float4* p, int n) {
    int i = blockIdx.x * blockDim.x + threadIdx.x;
    if (i < n) p[i] = make_float4(0.f, 0.f, 0.f, 0.f);
}
__global__ void k_filli4(int4* p, int n, int v) {
    int i = blockIdx.x * blockDim.x + threadIdx.x;
    if (i < n) p[i] = make_int4(v, v, v, v);
}

// ---------------- CSR build ----------------
__global__ void k_hist(const int* __restrict__ obj) {
    int i = blockIdx.x * blockDim.x + threadIdx.x;
    if (i >= LNUM * ENUM) return;
    int layer = i / ENUM;
    atomicAdd(&g_cnt[layer * NNODE + obj[i]], 1);
}

__global__ void k_scan() {
    __shared__ int sm[1024];
    int layer = blockIdx.x;
    int t = threadIdx.x;
    const int CH = (NNODE + 1023) / 1024;
    int b0 = t * CH;
    int b1 = b0 + CH;
    if (b1 > NNODE) b1 = NNODE;
    if (b0 > NNODE) b0 = NNODE;
    const int* c = g_cnt + layer * NNODE;
    int s = 0;
    for (int i = b0; i < b1; i++) s += c[i];
    sm[t] = s;
    __syncthreads();
    for (int off = 1; off < 1024; off <<= 1) {
        int u = (t >= off) ? sm[t - off] : 0;
        __syncthreads();
        sm[t] += u;
        __syncthreads();
    }
    int run = sm[t] - s;  // exclusive prefix of this thread's chunk
    int* R = g_rs + layer * (NNODE + 1);
    int* RW = g_rsw + layer * NNODE;
    for (int i = b0; i < b1; i++) {
        R[i] = run;
        RW[i] = run;
        run += c[i];
    }
    if (b1 == NNODE && b0 < NNODE) R[NNODE] = ENUM;
}

__global__ void k_perm(const int* __restrict__ sub, const int* __restrict__ rel,
                       const int* __restrict__ ridx, const int* __restrict__ obj) {
    int i = blockIdx.x * blockDim.x + threadIdx.x;
    if (i >= LNUM * ENUM) return;
    int layer = i / ENUM;
    int o = obj[i];
    int pos = atomicAdd(&g_rsw[layer * NNODE + o], 1);
    g_epack[(size_t)layer * ENUM + pos] = make_int4(sub[i], rel[i], ridx[i], 0);
}

// ---------------- B-fragment precompute (tf32, mma-swizzled) ----------------
__device__ __forceinline__ float bval(const float* W, int e, int NT) {
    int j = e & 1;
    int lane = (e >> 1) & 31;
    int nk = e >> 6;
    int ntg = nk % NT;
    int ks = nk / NT;
    int n = ntg * 8 + (lane >> 2);
    int k = ks * 8 + (lane & 3) + 4 * j;
    return __uint_as_float(f2tf(W[n * 64 + k]));
}
__global__ void k_bfrag(const float* __restrict__ Wh, const float* __restrict__ Wih,
                        const float* __restrict__ Whh) {
    int i = blockIdx.x * blockDim.x + threadIdx.x;
    const int WH = 4096, WI = 12288;
    if (i < 3 * WH) {
        int layer = i / WH, e = i % WH;
        g_bWh[i] = bval(Wh + layer * 4096, e, 8);
    } else if (i < 3 * WH + WI) {
        int e = i - 3 * WH;
        g_bWih[e] = bval(Wih, e, 24);
    } else if (i < 3 * WH + 2 * WI) {
        int e = i - 3 * WH - WI;
        g_bWhh[e] = bval(Whh, e, 24);
    }
}

// ---------------- per-layer projections: node/rel/query-rel -> 8 attn dims ----
__global__ void k_proj(const float* __restrict__ emb, const float* __restrict__ Ws,
                       const float* __restrict__ Wr, const float* __restrict__ Wqr,
                       const float* __restrict__ Wqrb, const int* __restrict__ relation,
                       int wbase) {
    int w = ((blockIdx.x * blockDim.x + threadIdx.x) >> 5) + wbase;
    int lane = threadIdx.x & 31;
    const int R = NNODE + NR2C + QNUM;
    if (w >= R) return;
    const float* src;
    const float* W;
    float* dst;
    bool isQ = false;
    if (w < NNODE) {
        src = g_state + (size_t)w * 64; W = Ws; dst = g_nproj + w * 8;
    } else if (w < NNODE + NR2C) {
        int r = w - NNODE;
        src = emb + (size_t)r * 64; W = Wr; dst = g_rproj + r * 8;
    } else {
        int q = w - NNODE - NR2C;
        src = emb + (size_t)relation[q] * 64; W = Wqr; dst = g_qproj + q * 8;
        isQ = true;
    }
    float2 s2 = ((const float2*)src)[lane];
    float res = 0.f;
#pragma unroll
    for (int a = 0; a < 8; a++) {
        float2 w2 = __ldg((const float2*)(W + a * 64) + lane);
        float p = s2.x * w2.x + s2.y * w2.y;
#pragma unroll
        for (int m = 16; m >= 1; m >>= 1) p += __shfl_xor_sync(0xffffffffu, p, m);
        if (lane == a) res = p;
    }
    if (lane < 8) dst[lane] = res + (isQ ? Wqrb[lane] : 0.f);
}

// ---------------- CSR aggregation: agg[o] = sum alpha*(hs+hr) ----------------
// 16 threads per node; each owns one float4 (16 x 16B = 256B row).
template <bool HS>
__global__ void __launch_bounds__(256) k_agg(const int* __restrict__ rs,
                                             const int4* __restrict__ epack,
                                             const float* __restrict__ emb,
                                             const float* __restrict__ wal,
                                             const float* __restrict__ walb) {
    int g = (blockIdx.x * 256 + threadIdx.x) >> 4;  // node id
    if (g >= NNODE) return;
    int sl = threadIdx.x & 15;
    unsigned gmask = 0xFFFFu << (threadIdx.x & 16);
    int beg = rs[g], end = rs[g + 1];
    float wa = (sl < 8) ? __ldg(wal + sl) : 0.f;
    float wb = __ldg(walb);
    const float4* st4 = (const float4*)g_state;
    const float4* em4 = (const float4*)emb;
    float4 acc = make_float4(0.f, 0.f, 0.f, 0.f);

    for (int j = beg; j < end; j++) {
        int4 e = __ldg(epack + j);   // (sub, rel, ridx, 0) broadcast within group
        float p = 0.f;
        if (sl < 8) {
            float t = g_rproj[e.y * 8 + sl] + g_qproj[e.z * 8 + sl];
            if (HS) t += g_nproj[e.x * 8 + sl];
            p = fmaxf(t, 0.f) * wa;
        }
        p += __shfl_xor_sync(gmask, p, 1);
        p += __shfl_xor_sync(gmask, p, 2);
        p += __shfl_xor_sync(gmask, p, 4);
        p += __shfl_xor_sync(gmask, p, 8);
        float alpha = sigf(p + wb);
        float4 hr = em4[e.y * 16 + sl];
        if (HS) {
            float4 hs = st4[(size_t)e.x * 16 + sl];
            acc.x = fmaf(alpha, hs.x + hr.x, acc.x);
            acc.y = fmaf(alpha, hs.y + hr.y, acc.y);
            acc.z = fmaf(alpha, hs.z + hr.z, acc.z);
            acc.w = fmaf(alpha, hs.w + hr.w, acc.w);
        } else {
            acc.x = fmaf(alpha, hr.x, acc.x);
            acc.y = fmaf(alpha, hr.y, acc.y);
            acc.z = fmaf(alpha, hr.z, acc.z);
            acc.w = fmaf(alpha, hr.w, acc.w);
        }
    }
    ((float4*)g_agg)[(size_t)g * 16 + sl] = acc;
}

// ---------------- fused node phase: X=relu(agg@Wh^T); GRU(X, state) ----------
template <bool FIRST>
__global__ void __launch_bounds__(256, 2)
k_fused(const float* __restrict__ Ap, const float* __restrict__ BWh,
        const float* __restrict__ BWih, const float* __restrict__ BWhh,
        const float* __restrict__ bih, const float* __restrict__ bhh) {
    __shared__ float As[32][68];
    __shared__ float Xs[32][68];
    __shared__ float Ss[32][68];
    int t = threadIdx.x;
    int warp = t >> 5, lane = t & 31;
    int wr = warp >> 2, wc = warp & 3;
    int tg = lane >> 2, tig = lane & 3;
    int m0 = blockIdx.x * 32;

#pragma unroll
    for (int p = 0; p < 2; p++) {
        int idx = t + p * 256;
        int r = idx >> 4, c4 = idx & 15;
        float4 v = *((const float4*)(Ap + (size_t)(m0 + r) * 64) + c4);
        As[r][c4 * 4 + 0] = tf(v.x);
        As[r][c4 * 4 + 1] = tf(v.y);
        As[r][c4 * 4 + 2] = tf(v.z);
        As[r][c4 * 4 + 3] = tf(v.w);
        if (!FIRST) {
            float4 s = *((const float4*)(g_state + (size_t)(m0 + r) * 64) + c4);
            Ss[r][c4 * 4 + 0] = tf(s.x);
            Ss[r][c4 * 4 + 1] = tf(s.y);
            Ss[r][c4 * 4 + 2] = tf(s.z);
            Ss[r][c4 * 4 + 3] = tf(s.w);
        }
    }
    __syncthreads();

    // --- X = relu(agg @ Wh^T), 64 cols ---
    {
        float accx[2][4] = {};
#pragma unroll
        for (int ks = 0; ks < 8; ks++) {
            int k0 = ks * 8;
            unsigned a0 = __float_as_uint(As[wr * 16 + tg][k0 + tig]);
            unsigned a1 = __float_as_uint(As[wr * 16 + tg + 8][k0 + tig]);
            unsigned a2 = __float_as_uint(As[wr * 16 + tg][k0 + tig + 4]);
            unsigned a3 = __float_as_uint(As[wr * 16 + tg + 8][k0 + tig + 4]);
#pragma unroll
            for (int cg = 0; cg < 2; cg++) {
                int ntg = wc * 2 + cg;
                float2 b = *(const float2*)(BWh + (((size_t)ks * 8 + ntg) * 32 + lane) * 2);
                mma8(accx[cg], a0, a1, a2, a3, __float_as_uint(b.x), __float_as_uint(b.y));
            }
        }
        __syncthreads();
        int rl = wr * 16 + tg;
#pragma unroll
        for (int cg = 0; cg < 2; cg++) {
            int col = (wc * 2 + cg) * 8 + 2 * tig;
            Xs[rl][col]         = tf(fmaxf(accx[cg][0], 0.f));
            Xs[rl][col + 1]     = tf(fmaxf(accx[cg][1], 0.f));
            Xs[rl + 8][col]     = tf(fmaxf(accx[cg][2], 0.f));
            Xs[rl + 8][col + 1] = tf(fmaxf(accx[cg][3], 0.f));
        }
        __syncthreads();
    }

    // --- gates ---
    float acc_r[2][4] = {}, acc_z[2][4] = {}, acc_ni[2][4] = {}, acc_nh[2][4] = {};
#pragma unroll
    for (int ks = 0; ks < 8; ks++) {
        int k0 = ks * 8;
        unsigned x0 = __float_as_uint(Xs[wr * 16 + tg][k0 + tig]);
        unsigned x1 = __float_as_uint(Xs[wr * 16 + tg + 8][k0 + tig]);
        unsigned x2 = __float_as_uint(Xs[wr * 16 + tg][k0 + tig + 4]);
        unsigned x3 = __float_as_uint(Xs[wr * 16 + tg + 8][k0 + tig + 4]);
        unsigned s0 = 0, s1 = 0, s2 = 0, s3 = 0;
        if (!FIRST) {
            s0 = __float_as_uint(Ss[wr * 16 + tg][k0 + tig]);
            s1 = __float_as_uint(Ss[wr * 16 + tg + 8][k0 + tig]);
            s2 = __float_as_uint(Ss[wr * 16 + tg][k0 + tig + 4]);
            s3 = __float_as_uint(Ss[wr * 16 + tg + 8][k0 + tig + 4]);
        }
#pragma unroll
        for (int cg = 0; cg < 2; cg++) {
            int nb = wc * 2 + cg;
#pragma unroll
            for (int g = 0; g < 3; g++) {
                int ntg = g * 8 + nb;
                float2 bi = *(const float2*)(BWih + (((size_t)ks * 24 + ntg) * 32 + lane) * 2);
                float* acc = (g == 0) ? acc_r[cg] : (g == 1) ? acc_z[cg] : acc_ni[cg];
                mma8(acc, x0, x1, x2, x3, __float_as_uint(bi.x), __float_as_uint(bi.y));
                if (!FIRST) {
                    float2 bh = *(const float2*)(BWhh + (((size_t)ks * 24 + ntg) * 32 + lane) * 2);
                    float* acch = (g == 0) ? acc_r[cg] : (g == 1) ? acc_z[cg] : acc_nh[cg];
                    mma8(acch, s0, s1, s2, s3, __float_as_uint(bh.x), __float_as_uint(bh.y));
                }
            }
        }
    }

    // --- GRU epilogue ---
    int r0 = m0 + wr * 16 + tg;
#pragma unroll
    for (int cg = 0; cg < 2; cg++) {
        int col = (wc * 2 + cg) * 8 + 2 * tig;
        float2 bi_r = __ldg((const float2*)(bih + col));
        float2 bh_r = __ldg((const float2*)(bhh + col));
        float2 bi_z = __ldg((const float2*)(bih + 64 + col));
        float2 bh_z = __ldg((const float2*)(bhh + 64 + col));
        float2 bi_n = __ldg((const float2*)(bih + 128 + col));
        float2 bh_n = __ldg((const float2*)(bhh + 128 + col));
        float2 h0v = make_float2(0.f, 0.f), h1v = make_float2(0.f, 0.f);
        if (!FIRST) {
            h0v = *(const float2*)(g_state + (size_t)r0 * 64 + col);
            h1v = *(const float2*)(g_state + (size_t)(r0 + 8) * 64 + col);
        }
#define GRU1(ai, bx, hy, outv)                                                  \
        {                                                                       \
            float rr = sigf(acc_r[cg][ai] + bi_r.bx + bh_r.bx);                 \
            float zz = sigf(acc_z[cg][ai] + bi_z.bx + bh_z.bx);                 \
            float nn = tanhf(acc_ni[cg][ai] + bi_n.bx +                         \
                             rr * (acc_nh[cg][ai] + bh_n.bx));                  \
            outv = (1.f - zz) * nn + zz * hy;                                   \
        }
        float2 o0, o1;
        GRU1(0, x, h0v.x, o0.x)
        GRU1(1, y, h0v.y, o0.y)
        GRU1(2, x, h1v.x, o1.x)
        GRU1(3, y, h1v.y, o1.y)
#undef GRU1
        *(float2*)(g_state + (size_t)r0 * 64 + col) = o0;
        *(float2*)(g_state + (size_t)(r0 + 8) * 64 + col) = o1;
    }
}

// ---------------- final score + deterministic scatter ----------------
__global__ void k_score(const float* __restrict__ wf, const int* __restrict__ nq,
                        const int* __restrict__ ne) {
    int w = (blockIdx.x * blockDim.x + threadIdx.x) >> 5;
    int lane = threadIdx.x & 31;
    if (w >= NNODE) return;
    float2 s2 = ((const float2*)(g_state + (size_t)w * 64))[lane];
    float2 w2 = __ldg((const float2*)wf + lane);
    float p = s2.x * w2.x + s2.y * w2.y;
#pragma unroll
    for (int m = 16; m >= 1; m >>= 1) p += __shfl_xor_sync(0xffffffffu, p, m);
    if (lane == 0) {
        g_scores[w] = p;
        int slot = nq[w] * ENTC + ne[w];
        atomicMax(&g_winner[slot], w);
    }
}
__global__ void k_scatter(const int* __restrict__ nq, const int* __restrict__ ne,
                          float* __restrict__ out) {
    int n = blockIdx.x * blockDim.x + threadIdx.x;
    if (n >= NNODE) return;
    int slot = nq[n] * ENTC + ne[n];
    if (g_winner[slot] == n) out[slot] = g_scores[n];
}

// ---------------- host launch ----------------
extern "C" void kernel_launch(void* const* d_in, const int* in_sizes, int n_in,
                              void* d_out, int out_size) {
    const int* relation = (const int*)d_in[0];
    const int* r_idx    = (const int*)d_in[1];
    const int* rel      = (const int*)d_in[2];
    const int* sub      = (const int*)d_in[3];
    const int* obj      = (const int*)d_in[4];
    const int* nq       = (const int*)d_in[6];
    const int* ne       = (const int*)d_in[7];
    const float* rela   = (const float*)d_in[8];
    const float* Ws     = (const float*)d_in[9];
    const float* Wr     = (const float*)d_in[10];
    const float* Wqr    = (const float*)d_in[11];
    const float* Wqrb   = (const float*)d_in[12];
    const float* wal    = (const float*)d_in[13];
    const float* walb   = (const float*)d_in[14];
    const float* Wh     = (const float*)d_in[15];
    const float* Wih    = (const float*)d_in[16];
    const float* Whh    = (const float*)d_in[17];
    const float* bih    = (const float*)d_in[18];
    const float* bhh    = (const float*)d_in[19];
    const float* Wfin   = (const float*)d_in[20];
    float* out = (float*)d_out;

    float *p_state, *p_agg, *p_bWh, *p_bWih, *p_bWhh;
    int *p_win, *p_cnt, *p_rs;
    int4* p_epack;
    cudaGetSymbolAddress((void**)&p_state, g_state);
    cudaGetSymbolAddress((void**)&p_agg, g_agg);
    cudaGetSymbolAddress((void**)&p_bWh, g_bWh);
    cudaGetSymbolAddress((void**)&p_bWih, g_bWih);
    cudaGetSymbolAddress((void**)&p_bWhh, g_bWhh);
    cudaGetSymbolAddress((void**)&p_win, g_winner);
    cudaGetSymbolAddress((void**)&p_cnt, g_cnt);
    cudaGetSymbolAddress((void**)&p_rs, g_rs);
    cudaGetSymbolAddress((void**)&p_epack, g_epack);

    const int TB = 256;
    k_zero4<<<(NNODE * 16 + TB - 1) / TB, TB>>>((float4*)p_state, NNODE * 16);
    k_zero4<<<(QNUM * ENTC / 4 + TB - 1) / TB, TB>>>((float4*)out, QNUM * ENTC / 4);
    k_filli4<<<(QNUM * ENTC / 4 + TB - 1) / TB, TB>>>((int4*)p_win, QNUM * ENTC / 4, -1);
    k_zero4<<<(LNUM * NNODE / 4 + TB - 1) / TB, TB>>>((float4*)p_cnt, LNUM * NNODE / 4);
    k_bfrag<<<144, TB>>>(Wh, Wih, Whh);

    // CSR build for all layers
    k_hist<<<(LNUM * ENUM + TB - 1) / TB, TB>>>(obj);
    k_scan<<<LNUM, 1024>>>();
    k_perm<<<(LNUM * ENUM + TB - 1) / TB, TB>>>(sub, rel, r_idx, obj);

    for (int i = 0; i < LNUM; i++) {
        const float* emb = rela + (size_t)i * NR2C * DDIM;
        const int* rs_i = p_rs + i * (NNODE + 1);
        const int4* ep_i = p_epack + (size_t)i * ENUM;
        if (i == 0) {
            int R = NR2C + QNUM;
            k_proj<<<(R * 32 + TB - 1) / TB, TB>>>(emb, Ws + i * 512, Wr + i * 512,
                                                   Wqr + i * 512, Wqrb + i * 8, relation,
                                                   NNODE);
            k_agg<false><<<(NNODE * 16 + TB - 1) / TB, TB>>>(rs_i, ep_i, emb,
                                                             wal + i * 8, walb + i);
            k_fused<true><<<NNODE / 32, TB>>>(p_agg, p_bWh + i * 4096, p_bWih, p_bWhh,
                                              bih, bhh);
        } else {
            int R = NNODE + NR2C + QNUM;
            k_proj<<<(R * 32 + TB - 1) / TB, TB>>>(emb, Ws + i * 512, Wr + i * 512,
                                                   Wqr + i * 512, Wqrb + i * 8, relation, 0);
            k_agg<true><<<(NNODE * 16 + TB - 1) / TB, TB>>>(rs_i, ep_i, emb,
                                                            wal + i * 8, walb + i);
            k_fused<false><<<NNODE / 32, TB>>>(p_agg, p_bWh + i * 4096, p_bWih, p_bWhh,
                                               bih, bhh);
        }
    }

    k_score<<<(NNODE * 32 + TB - 1) / TB, TB>>>(Wfin, nq, ne);
    k_scatter<<<(NNODE + TB - 1) / TB, TB>>>(nq, ne, out);
}

// round 6
// speedup vs baseline: 1.2412x; 1.2412x over previous
#include <cuda_runtime.h>

#define LNUM 3
#define ENUM 1000000
#define NNODE 100000
#define DDIM 64
#define ADIM 8
#define NR2C 461
#define QNUM 1000
#define ENTC 10000

// ---------------- scratch (device globals; no allocation) ----------------
__device__ float g_state[NNODE * DDIM];
__device__ float g_agg[NNODE * DDIM];
__device__ float g_nproj[NNODE * ADIM];
__device__ float g_rproj[LNUM * NR2C * ADIM];
__device__ float g_qproj[LNUM * QNUM * ADIM];
__device__ float g_bWh[LNUM * 4096];    // per-layer 8ks x 8nt x 32 x 2
__device__ float g_bWih[12288];         // 8ks x 24nt x 32 x 2
__device__ float g_bWhh[12288];
__device__ float g_bWs[LNUM * 512];     // per-layer 8ks x 1nt x 32 x 2
__device__ float g_scores[NNODE];
__device__ int   g_winner[QNUM * ENTC];

// ---------------- helpers ----------------
__device__ __forceinline__ unsigned f2tf(float x) {
    unsigned u;
    asm("cvt.rna.tf32.f32 %0, %1;" : "=r"(u) : "f"(x));
    return u;
}
__device__ __forceinline__ float tf(float x) { return __uint_as_float(f2tf(x)); }
__device__ __forceinline__ float sigf(float x) { return 1.f / (1.f + __expf(-x)); }

__device__ __forceinline__ void mma8(float acc[4], unsigned a0, unsigned a1,
                                     unsigned a2, unsigned a3, unsigned b0, unsigned b1) {
    asm volatile(
        "mma.sync.aligned.m16n8k8.row.col.f32.tf32.tf32.f32 "
        "{%0,%1,%2,%3}, {%4,%5,%6,%7}, {%8,%9}, {%0,%1,%2,%3};"
        : "+f"(acc[0]), "+f"(acc[1]), "+f"(acc[2]), "+f"(acc[3])
        : "r"(a0), "r"(a1), "r"(a2), "r"(a3), "r"(b0), "r"(b1));
}

// ---------------- consolidated init ----------------
__global__ void k_init(float4* out4) {
    int i = blockIdx.x * blockDim.x + threadIdx.x;
    const int NS = NNODE * 16;           // f4 count of state (=agg)
    const int NO = QNUM * ENTC / 4;      // f4 count of out (=winner)
    float4 z = make_float4(0.f, 0.f, 0.f, 0.f);
    if (i < NS) {
        ((float4*)g_state)[i] = z;
        ((float4*)g_agg)[i] = z;
    }
    if (i < NO) {
        out4[i] = z;
        ((int4*)g_winner)[i] = make_int4(-1, -1, -1, -1);
    }
}

// ---------------- B-fragment precompute (tf32, mma-swizzled) ----------------
__device__ __forceinline__ float bval(const float* W, int e, int NT) {
    int j = e & 1;
    int lane = (e >> 1) & 31;
    int nk = e >> 6;
    int ntg = nk % NT;
    int ks = nk / NT;
    int n = ntg * 8 + (lane >> 2);
    int k = ks * 8 + (lane & 3) + 4 * j;
    return __uint_as_float(f2tf(W[n * 64 + k]));
}
__global__ void k_bfrag(const float* __restrict__ Wh, const float* __restrict__ Wih,
                        const float* __restrict__ Whh, const float* __restrict__ Ws) {
    int i = blockIdx.x * blockDim.x + threadIdx.x;
    const int WH = 4096, WI = 12288, WS = 512;
    if (i < 3 * WH) {
        int layer = i / WH, e = i % WH;
        g_bWh[i] = bval(Wh + layer * 4096, e, 8);
    } else if (i < 3 * WH + WI) {
        int e = i - 3 * WH;
        g_bWih[e] = bval(Wih, e, 24);
    } else if (i < 3 * WH + 2 * WI) {
        int e = i - 3 * WH - WI;
        g_bWhh[e] = bval(Whh, e, 24);
    } else if (i < 3 * WH + 2 * WI + 3 * WS) {
        int e = i - 3 * WH - 2 * WI;
        int layer = e / WS, ee = e % WS;
        g_bWs[e] = bval(Ws + layer * 512, ee, 1);
    }
}

// ---------------- rel/query projections for ALL layers (state-independent) ---
__global__ void k_projRQ(const float* __restrict__ rela, const float* __restrict__ Wr,
                         const float* __restrict__ Wqr, const float* __restrict__ Wqrb,
                         const int* __restrict__ relation) {
    int w = (blockIdx.x * blockDim.x + threadIdx.x) >> 5;
    int lane = threadIdx.x & 31;
    const int PER = NR2C + QNUM;
    if (w >= LNUM * PER) return;
    int layer = w / PER;
    int r = w % PER;
    const float* emb = rela + (size_t)layer * NR2C * DDIM;
    const float* src;
    const float* W;
    float* dst;
    bool isQ;
    if (r < NR2C) {
        src = emb + (size_t)r * 64; W = Wr + layer * 512;
        dst = g_rproj + (layer * NR2C + r) * 8; isQ = false;
    } else {
        int q = r - NR2C;
        src = emb + (size_t)__ldg(relation + q) * 64; W = Wqr + layer * 512;
        dst = g_qproj + (layer * QNUM + q) * 8; isQ = true;
    }
    float2 s2 = ((const float2*)src)[lane];
    float res = 0.f;
#pragma unroll
    for (int a = 0; a < 8; a++) {
        float2 w2 = __ldg((const float2*)(W + a * 64) + lane);
        float p = s2.x * w2.x + s2.y * w2.y;
#pragma unroll
        for (int m = 16; m >= 1; m >>= 1) p += __shfl_xor_sync(0xffffffffu, p, m);
        if (lane == a) res = p;
    }
    if (lane < 8) dst[lane] = res + (isQ ? __ldg(Wqrb + layer * 8 + lane) : 0.f);
}

// ---------------- edge kernel: attention + scatter-add message ----------------
template <bool HS>
__global__ void k_edge(const int* __restrict__ sub, const int* __restrict__ rel,
                       const int* __restrict__ ridx, const int* __restrict__ obj,
                       const float* __restrict__ emb, const float* __restrict__ wal,
                       const float* __restrict__ walb, const float* __restrict__ rproj,
                       const float* __restrict__ qproj) {
    int gt = blockIdx.x * blockDim.x + threadIdx.x;
    int e = gt >> 2;
    if (e >= ENUM) return;
    int lq = threadIdx.x & 3;
    int r = __ldg(rel + e), q = __ldg(ridx + e), o = __ldg(obj + e);
    int s = HS ? __ldg(sub + e) : 0;
    float wb = __ldg(walb);

    float part = 0.f;
#pragma unroll
    for (int u = 0; u < 2; u++) {
        int a = lq * 2 + u;
        float t = __ldg(rproj + r * 8 + a) + __ldg(qproj + q * 8 + a);
        if (HS) t += g_nproj[s * 8 + a];
        part = fmaf(fmaxf(t, 0.f), __ldg(wal + a), part);
    }
    part += __shfl_xor_sync(0xffffffffu, part, 1);
    part += __shfl_xor_sync(0xffffffffu, part, 2);
    float alpha = sigf(part + wb);

    const float4* hs4 = (const float4*)(g_state + (size_t)s * 64);
    const float4* hr4 = (const float4*)(emb + (size_t)r * 64);
    float* ap = g_agg + (size_t)o * 64 + lq * 16;
#pragma unroll
    for (int c = 0; c < 4; c++) {
        float4 b4 = hr4[lq * 4 + c];
        float mx, my, mz, mw;
        if (HS) {
            float4 a4 = hs4[lq * 4 + c];
            mx = alpha * (a4.x + b4.x);
            my = alpha * (a4.y + b4.y);
            mz = alpha * (a4.z + b4.z);
            mw = alpha * (a4.w + b4.w);
        } else {
            mx = alpha * b4.x; my = alpha * b4.y;
            mz = alpha * b4.z; mw = alpha * b4.w;
        }
        asm volatile("red.global.add.v4.f32 [%0], {%1,%2,%3,%4};"
                     :: "l"(ap + c * 4), "f"(mx), "f"(my), "f"(mz), "f"(mw)
                     : "memory");
    }
}

// ---------------- fused node phase + next-layer nproj + agg re-zero ----------
template <bool FIRST, bool PROJ>
__global__ void __launch_bounds__(256, 2)
k_fused(const float* __restrict__ BWh, const float* __restrict__ BWih,
        const float* __restrict__ BWhh, const float* __restrict__ BWs,
        const float* __restrict__ bih, const float* __restrict__ bhh) {
    __shared__ float As[32][68];
    __shared__ float Xs[32][68];
    __shared__ float Ss[32][68];
    int t = threadIdx.x;
    int warp = t >> 5, lane = t & 31;
    int wr = warp >> 2, wc = warp & 3;
    int tg = lane >> 2, tig = lane & 3;
    int m0 = blockIdx.x * 32;

#pragma unroll
    for (int p = 0; p < 2; p++) {
        int idx = t + p * 256;
        int r = idx >> 4, c4 = idx & 15;
        float4 v = *((const float4*)(g_agg + (size_t)(m0 + r) * 64) + c4);
        As[r][c4 * 4 + 0] = tf(v.x);
        As[r][c4 * 4 + 1] = tf(v.y);
        As[r][c4 * 4 + 2] = tf(v.z);
        As[r][c4 * 4 + 3] = tf(v.w);
        if (!FIRST) {
            float4 s = *((const float4*)(g_state + (size_t)(m0 + r) * 64) + c4);
            Ss[r][c4 * 4 + 0] = tf(s.x);
            Ss[r][c4 * 4 + 1] = tf(s.y);
            Ss[r][c4 * 4 + 2] = tf(s.z);
            Ss[r][c4 * 4 + 3] = tf(s.w);
        }
    }
    __syncthreads();

    // --- X = relu(agg @ Wh^T) ---
    {
        float accx[2][4] = {};
#pragma unroll
        for (int ks = 0; ks < 8; ks++) {
            int k0 = ks * 8;
            unsigned a0 = __float_as_uint(As[wr * 16 + tg][k0 + tig]);
            unsigned a1 = __float_as_uint(As[wr * 16 + tg + 8][k0 + tig]);
            unsigned a2 = __float_as_uint(As[wr * 16 + tg][k0 + tig + 4]);
            unsigned a3 = __float_as_uint(As[wr * 16 + tg + 8][k0 + tig + 4]);
#pragma unroll
            for (int cg = 0; cg < 2; cg++) {
                int ntg = wc * 2 + cg;
                float2 b = *(const float2*)(BWh + (((size_t)ks * 8 + ntg) * 32 + lane) * 2);
                mma8(accx[cg], a0, a1, a2, a3, __float_as_uint(b.x), __float_as_uint(b.y));
            }
        }
        __syncthreads();
        int rl = wr * 16 + tg;
#pragma unroll
        for (int cg = 0; cg < 2; cg++) {
            int col = (wc * 2 + cg) * 8 + 2 * tig;
            Xs[rl][col]         = tf(fmaxf(accx[cg][0], 0.f));
            Xs[rl][col + 1]     = tf(fmaxf(accx[cg][1], 0.f));
            Xs[rl + 8][col]     = tf(fmaxf(accx[cg][2], 0.f));
            Xs[rl + 8][col + 1] = tf(fmaxf(accx[cg][3], 0.f));
        }
        __syncthreads();
    }

    // --- gates ---
    float acc_r[2][4] = {}, acc_z[2][4] = {}, acc_ni[2][4] = {}, acc_nh[2][4] = {};
#pragma unroll
    for (int ks = 0; ks < 8; ks++) {
        int k0 = ks * 8;
        unsigned x0 = __float_as_uint(Xs[wr * 16 + tg][k0 + tig]);
        unsigned x1 = __float_as_uint(Xs[wr * 16 + tg + 8][k0 + tig]);
        unsigned x2 = __float_as_uint(Xs[wr * 16 + tg][k0 + tig + 4]);
        unsigned x3 = __float_as_uint(Xs[wr * 16 + tg + 8][k0 + tig + 4]);
        unsigned s0 = 0, s1 = 0, s2 = 0, s3 = 0;
        if (!FIRST) {
            s0 = __float_as_uint(Ss[wr * 16 + tg][k0 + tig]);
            s1 = __float_as_uint(Ss[wr * 16 + tg + 8][k0 + tig]);
            s2 = __float_as_uint(Ss[wr * 16 + tg][k0 + tig + 4]);
            s3 = __float_as_uint(Ss[wr * 16 + tg + 8][k0 + tig + 4]);
        }
#pragma unroll
        for (int cg = 0; cg < 2; cg++) {
            int nb = wc * 2 + cg;
#pragma unroll
            for (int g = 0; g < 3; g++) {
                int ntg = g * 8 + nb;
                float2 bi = *(const float2*)(BWih + (((size_t)ks * 24 + ntg) * 32 + lane) * 2);
                float* acc = (g == 0) ? acc_r[cg] : (g == 1) ? acc_z[cg] : acc_ni[cg];
                mma8(acc, x0, x1, x2, x3, __float_as_uint(bi.x), __float_as_uint(bi.y));
                if (!FIRST) {
                    float2 bh = *(const float2*)(BWhh + (((size_t)ks * 24 + ntg) * 32 + lane) * 2);
                    float* acch = (g == 0) ? acc_r[cg] : (g == 1) ? acc_z[cg] : acc_nh[cg];
                    mma8(acch, s0, s1, s2, s3, __float_as_uint(bh.x), __float_as_uint(bh.y));
                }
            }
        }
    }

    if (PROJ) __syncthreads();  // all gate-mma reads of Ss done before overwrite

    // --- GRU epilogue (+ stash new state tf32 in Ss when PROJ) ---
    int r0 = m0 + wr * 16 + tg;
#pragma unroll
    for (int cg = 0; cg < 2; cg++) {
        int col = (wc * 2 + cg) * 8 + 2 * tig;
        float2 bi_r = __ldg((const float2*)(bih + col));
        float2 bh_r = __ldg((const float2*)(bhh + col));
        float2 bi_z = __ldg((const float2*)(bih + 64 + col));
        float2 bh_z = __ldg((const float2*)(bhh + 64 + col));
        float2 bi_n = __ldg((const float2*)(bih + 128 + col));
        float2 bh_n = __ldg((const float2*)(bhh + 128 + col));
        float2 h0v = make_float2(0.f, 0.f), h1v = make_float2(0.f, 0.f);
        if (!FIRST) {
            h0v = *(const float2*)(g_state + (size_t)r0 * 64 + col);
            h1v = *(const float2*)(g_state + (size_t)(r0 + 8) * 64 + col);
        }
#define GRU1(ai, bx, hy, outv)                                                  \
        {                                                                       \
            float rr = sigf(acc_r[cg][ai] + bi_r.bx + bh_r.bx);                 \
            float zz = sigf(acc_z[cg][ai] + bi_z.bx + bh_z.bx);                 \
            float nn = tanhf(acc_ni[cg][ai] + bi_n.bx +                         \
                             rr * (acc_nh[cg][ai] + bh_n.bx));                  \
            outv = (1.f - zz) * nn + zz * hy;                                   \
        }
        float2 o0, o1;
        GRU1(0, x, h0v.x, o0.x)
        GRU1(1, y, h0v.y, o0.y)
        GRU1(2, x, h1v.x, o1.x)
        GRU1(3, y, h1v.y, o1.y)
#undef GRU1
        *(float2*)(g_state + (size_t)r0 * 64 + col) = o0;
        *(float2*)(g_state + (size_t)(r0 + 8) * 64 + col) = o1;
        if (PROJ) {
            int rl = wr * 16 + tg;
            Ss[rl][col] = tf(o0.x);
            Ss[rl][col + 1] = tf(o0.y);
            Ss[rl + 8][col] = tf(o1.x);
            Ss[rl + 8][col + 1] = tf(o1.y);
        }
    }

    if (PROJ) {
        __syncthreads();
        if (warp < 2) {
            // nproj = newstate @ Ws(next)^T : 32 rows x 8 cols
            float acc[4] = {};
#pragma unroll
            for (int ks = 0; ks < 8; ks++) {
                int k0 = ks * 8;
                unsigned a0 = __float_as_uint(Ss[warp * 16 + tg][k0 + tig]);
                unsigned a1 = __float_as_uint(Ss[warp * 16 + tg + 8][k0 + tig]);
                unsigned a2 = __float_as_uint(Ss[warp * 16 + tg][k0 + tig + 4]);
                unsigned a3 = __float_as_uint(Ss[warp * 16 + tg + 8][k0 + tig + 4]);
                float2 b = *(const float2*)(BWs + ((size_t)ks * 32 + lane) * 2);
                mma8(acc, a0, a1, a2, a3, __float_as_uint(b.x), __float_as_uint(b.y));
            }
            int row = m0 + warp * 16 + tg;
            *(float2*)(g_nproj + row * 8 + 2 * tig) = make_float2(acc[0], acc[1]);
            *(float2*)(g_nproj + (row + 8) * 8 + 2 * tig) = make_float2(acc[2], acc[3]);
        } else {
            // zero this block's agg slice for the next layer's edge kernel
            float4* a4 = (float4*)(g_agg + (size_t)m0 * 64);
            float4 z = make_float4(0.f, 0.f, 0.f, 0.f);
            for (int i = t - 64; i < 512; i += 192) a4[i] = z;
        }
    }
}

// ---------------- final score + deterministic scatter ----------------
__global__ void k_score(const float* __restrict__ wf, const int* __restrict__ nq,
                        const int* __restrict__ ne) {
    int w = (blockIdx.x * blockDim.x + threadIdx.x) >> 5;
    int lane = threadIdx.x & 31;
    if (w >= NNODE) return;
    float2 s2 = ((const float2*)(g_state + (size_t)w * 64))[lane];
    float2 w2 = __ldg((const float2*)wf + lane);
    float p = s2.x * w2.x + s2.y * w2.y;
#pragma unroll
    for (int m = 16; m >= 1; m >>= 1) p += __shfl_xor_sync(0xffffffffu, p, m);
    if (lane == 0) {
        g_scores[w] = p;
        int slot = __ldg(nq + w) * ENTC + __ldg(ne + w);
        atomicMax(&g_winner[slot], w);
    }
}
__global__ void k_scatter(const int* __restrict__ nq, const int* __restrict__ ne,
                          float* __restrict__ out) {
    int n = blockIdx.x * blockDim.x + threadIdx.x;
    if (n >= NNODE) return;
    int slot = __ldg(nq + n) * ENTC + __ldg(ne + n);
    if (g_winner[slot] == n) out[slot] = g_scores[n];
}

// ---------------- host launch ----------------
extern "C" void kernel_launch(void* const* d_in, const int* in_sizes, int n_in,
                              void* d_out, int out_size) {
    const int* relation = (const int*)d_in[0];
    const int* r_idx    = (const int*)d_in[1];
    const int* rel      = (const int*)d_in[2];
    const int* sub      = (const int*)d_in[3];
    const int* obj      = (const int*)d_in[4];
    const int* nq       = (const int*)d_in[6];
    const int* ne       = (const int*)d_in[7];
    const float* rela   = (const float*)d_in[8];
    const float* Ws     = (const float*)d_in[9];
    const float* Wr     = (const float*)d_in[10];
    const float* Wqr    = (const float*)d_in[11];
    const float* Wqrb   = (const float*)d_in[12];
    const float* wal    = (const float*)d_in[13];
    const float* walb   = (const float*)d_in[14];
    const float* Wh     = (const float*)d_in[15];
    const float* Wih    = (const float*)d_in[16];
    const float* Whh    = (const float*)d_in[17];
    const float* bih    = (const float*)d_in[18];
    const float* bhh    = (const float*)d_in[19];
    const float* Wfin   = (const float*)d_in[20];
    float* out = (float*)d_out;

    float *p_bWh, *p_bWih, *p_bWhh, *p_bWs, *p_rproj, *p_qproj;
    cudaGetSymbolAddress((void**)&p_bWh, g_bWh);
    cudaGetSymbolAddress((void**)&p_bWih, g_bWih);
    cudaGetSymbolAddress((void**)&p_bWhh, g_bWhh);
    cudaGetSymbolAddress((void**)&p_bWs, g_bWs);
    cudaGetSymbolAddress((void**)&p_rproj, g_rproj);
    cudaGetSymbolAddress((void**)&p_qproj, g_qproj);

    const int TB = 256;
    {
        int NS = NNODE * 16, NO = QNUM * ENTC / 4;
        int NI = NS > NO ? NS : NO;
        k_init<<<(NI + TB - 1) / TB, TB>>>((float4*)out);
    }
    k_bfrag<<<150, TB>>>(Wh, Wih, Whh, Ws);
    {
        int W = LNUM * (NR2C + QNUM);
        k_projRQ<<<(W * 32 + TB - 1) / TB, TB>>>(rela, Wr, Wqr, Wqrb, relation);
    }

    for (int i = 0; i < LNUM; i++) {
        const float* emb = rela + (size_t)i * NR2C * DDIM;
        const float* rp = p_rproj + i * NR2C * ADIM;
        const float* qp = p_qproj + i * QNUM * ADIM;
        if (i == 0) {
            k_edge<false><<<(ENUM * 4 + TB - 1) / TB, TB>>>(
                sub, rel, r_idx, obj, emb, wal, walb, rp, qp);
            k_fused<true, true><<<NNODE / 32, TB>>>(p_bWh, p_bWih, p_bWhh,
                                                    p_bWs + 512, bih, bhh);
        } else {
            k_edge<true><<<(ENUM * 4 + TB - 1) / TB, TB>>>(
                sub + (size_t)i * ENUM, rel + (size_t)i * ENUM, r_idx + (size_t)i * ENUM,
                obj + (size_t)i * ENUM, emb, wal + i * 8, walb + i, rp, qp);
            if (i + 1 < LNUM)
                k_fused<false, true><<<NNODE / 32, TB>>>(p_bWh + i * 4096, p_bWih, p_bWhh,
                                                         p_bWs + (i + 1) * 512, bih, bhh);
            else
                k_fused<false, false><<<NNODE / 32, TB>>>(p_bWh + i * 4096, p_bWih, p_bWhh,
                                                          p_bWs, bih, bhh);
        }
    }

    k_score<<<(NNODE * 32 + TB - 1) / TB, TB>>>(Wfin, nq, ne);
    k_scatter<<<(NNODE + TB - 1) / TB, TB>>>(nq, ne, out);
}

// round 7
// speedup vs baseline: 1.4622x; 1.1780x over previous
#include <cuda_runtime.h>

#define LNUM 3
#define ENUM 1000000
#define NNODE 100000
#define DDIM 64
#define ADIM 8
#define NR2C 461
#define QNUM 1000
#define ENTC 10000

// ---------------- scratch (device globals; no allocation) ----------------
__device__ float g_state[NNODE * DDIM];
__device__ float g_agg[NNODE * DDIM];
__device__ float g_nproj[NNODE * ADIM];
__device__ float g_rproj[LNUM * NR2C * ADIM];
__device__ float g_qproj[LNUM * QNUM * ADIM];
__device__ float g_alpha0[QNUM * NR2C];
__device__ float g_bWh[LNUM * 4096];    // per-layer 8ks x 8nt x 32 x 2
__device__ float g_bWih[12288];         // 8ks x 24nt x 32 x 2
__device__ float g_bWhh[12288];
__device__ float g_bWs[LNUM * 512];     // per-layer 8ks x 1nt x 32 x 2
__device__ float g_scores[NNODE];
__device__ int   g_winner[QNUM * ENTC];

// ---------------- helpers ----------------
__device__ __forceinline__ unsigned f2tf(float x) {
    unsigned u;
    asm("cvt.rna.tf32.f32 %0, %1;" : "=r"(u) : "f"(x));
    return u;
}
__device__ __forceinline__ float tf(float x) { return __uint_as_float(f2tf(x)); }
__device__ __forceinline__ float sigf(float x) { return 1.f / (1.f + __expf(-x)); }

__device__ __forceinline__ void mma8(float acc[4], unsigned a0, unsigned a1,
                                     unsigned a2, unsigned a3, unsigned b0, unsigned b1) {
    asm volatile(
        "mma.sync.aligned.m16n8k8.row.col.f32.tf32.tf32.f32 "
        "{%0,%1,%2,%3}, {%4,%5,%6,%7}, {%8,%9}, {%0,%1,%2,%3};"
        : "+f"(acc[0]), "+f"(acc[1]), "+f"(acc[2]), "+f"(acc[3])
        : "r"(a0), "r"(a1), "r"(a2), "r"(a3), "r"(b0), "r"(b1));
}

// ---------------- consolidated init ----------------
__global__ void k_init(float4* out4) {
    int i = blockIdx.x * blockDim.x + threadIdx.x;
    const int NS = NNODE * 16;           // f4 count of state (=agg)
    const int NO = QNUM * ENTC / 4;      // f4 count of out (=winner)
    float4 z = make_float4(0.f, 0.f, 0.f, 0.f);
    if (i < NS) {
        ((float4*)g_state)[i] = z;
        ((float4*)g_agg)[i] = z;
    }
    if (i < NO) {
        out4[i] = z;
        ((int4*)g_winner)[i] = make_int4(-1, -1, -1, -1);
    }
}

// ---------------- B-fragment precompute (tf32, mma-swizzled) ----------------
__device__ __forceinline__ float bval(const float* W, int e, int NT) {
    int j = e & 1;
    int lane = (e >> 1) & 31;
    int nk = e >> 6;
    int ntg = nk % NT;
    int ks = nk / NT;
    int n = ntg * 8 + (lane >> 2);
    int k = ks * 8 + (lane & 3) + 4 * j;
    return __uint_as_float(f2tf(W[n * 64 + k]));
}
__global__ void k_bfrag(const float* __restrict__ Wh, const float* __restrict__ Wih,
                        const float* __restrict__ Whh, const float* __restrict__ Ws) {
    int i = blockIdx.x * blockDim.x + threadIdx.x;
    const int WH = 4096, WI = 12288, WS = 512;
    if (i < 3 * WH) {
        int layer = i / WH, e = i % WH;
        g_bWh[i] = bval(Wh + layer * 4096, e, 8);
    } else if (i < 3 * WH + WI) {
        int e = i - 3 * WH;
        g_bWih[e] = bval(Wih, e, 24);
    } else if (i < 3 * WH + 2 * WI) {
        int e = i - 3 * WH - WI;
        g_bWhh[e] = bval(Whh, e, 24);
    } else if (i < 3 * WH + 2 * WI + 3 * WS) {
        int e = i - 3 * WH - 2 * WI;
        int layer = e / WS, ee = e % WS;
        g_bWs[e] = bval(Ws + layer * 512, ee, 1);
    }
}

// ---------------- rel/query projections for ALL layers (state-independent) ---
__global__ void k_projRQ(const float* __restrict__ rela, const float* __restrict__ Wr,
                         const float* __restrict__ Wqr, const float* __restrict__ Wqrb,
                         const int* __restrict__ relation) {
    int w = (blockIdx.x * blockDim.x + threadIdx.x) >> 5;
    int lane = threadIdx.x & 31;
    const int PER = NR2C + QNUM;
    if (w >= LNUM * PER) return;
    int layer = w / PER;
    int r = w % PER;
    const float* emb = rela + (size_t)layer * NR2C * DDIM;
    const float* src;
    const float* W;
    float* dst;
    bool isQ;
    if (r < NR2C) {
        src = emb + (size_t)r * 64; W = Wr + layer * 512;
        dst = g_rproj + (layer * NR2C + r) * 8; isQ = false;
    } else {
        int q = r - NR2C;
        src = emb + (size_t)__ldg(relation + q) * 64; W = Wqr + layer * 512;
        dst = g_qproj + (layer * QNUM + q) * 8; isQ = true;
    }
    float2 s2 = ((const float2*)src)[lane];
    float res = 0.f;
#pragma unroll
    for (int a = 0; a < 8; a++) {
        float2 w2 = __ldg((const float2*)(W + a * 64) + lane);
        float p = s2.x * w2.x + s2.y * w2.y;
#pragma unroll
        for (int m = 16; m >= 1; m >>= 1) p += __shfl_xor_sync(0xffffffffu, p, m);
        if (lane == a) res = p;
    }
    if (lane < 8) dst[lane] = res + (isQ ? __ldg(Wqrb + layer * 8 + lane) : 0.f);
}

// ---------------- layer-0 alpha table: alpha(q,r), hidden==0 -----------------
__global__ void k_alpha0(const float* __restrict__ wal, const float* __restrict__ walb) {
    int i = blockIdx.x * blockDim.x + threadIdx.x;
    if (i >= QNUM * NR2C) return;
    int q = i / NR2C, r = i % NR2C;
    float p = 0.f;
#pragma unroll
    for (int a = 0; a < 8; a++) {
        float t = g_rproj[r * 8 + a] + g_qproj[q * 8 + a];
        p = fmaf(fmaxf(t, 0.f), __ldg(wal + a), p);
    }
    g_alpha0[i] = sigf(p + __ldg(walb));
}

// ---------------- edge kernel: 16 lanes/edge, full-row coalesced -------------
template <bool HS>
__global__ void k_edge(const int* __restrict__ sub, const int* __restrict__ rel,
                       const int* __restrict__ ridx, const int* __restrict__ obj,
                       const float* __restrict__ emb, const float* __restrict__ wal,
                       const float* __restrict__ walb, const float* __restrict__ rproj,
                       const float* __restrict__ qproj) {
    int gt = blockIdx.x * blockDim.x + threadIdx.x;
    int e = gt >> 4;                      // edge id (ENUM*16 threads exactly)
    int sl = threadIdx.x & 15;            // lane within 16-group
    int r = __ldg(rel + e);
    int o = __ldg(obj + e);
    int q = __ldg(ridx + e);

    float alpha;
    if (HS) {
        int s = __ldg(sub + e);
        float p = 0.f;
        if (sl < 8) {
            float t = __ldg(rproj + r * 8 + sl) + __ldg(qproj + q * 8 + sl)
                    + g_nproj[s * 8 + sl];
            p = fmaxf(t, 0.f) * __ldg(wal + sl);
        }
        p += __shfl_xor_sync(0xffffffffu, p, 1);
        p += __shfl_xor_sync(0xffffffffu, p, 2);
        p += __shfl_xor_sync(0xffffffffu, p, 4);
        p += __shfl_xor_sync(0xffffffffu, p, 8);
        alpha = sigf(p + __ldg(walb));

        float4 hr = __ldg((const float4*)emb + r * 16 + sl);
        float4 hs = __ldg((const float4*)g_state + (size_t)s * 16 + sl);
        float mx = alpha * (hs.x + hr.x);
        float my = alpha * (hs.y + hr.y);
        float mz = alpha * (hs.z + hr.z);
        float mw = alpha * (hs.w + hr.w);
        asm volatile("red.global.add.v4.f32 [%0], {%1,%2,%3,%4};"
                     :: "l"(g_agg + (size_t)o * 64 + sl * 4),
                        "f"(mx), "f"(my), "f"(mz), "f"(mw) : "memory");
    } else {
        alpha = __ldg(g_alpha0 + q * NR2C + r);
        float4 hr = __ldg((const float4*)emb + r * 16 + sl);
        asm volatile("red.global.add.v4.f32 [%0], {%1,%2,%3,%4};"
                     :: "l"(g_agg + (size_t)o * 64 + sl * 4),
                        "f"(alpha * hr.x), "f"(alpha * hr.y),
                        "f"(alpha * hr.z), "f"(alpha * hr.w) : "memory");
    }
}

// ---------------- fused node phase + next-layer nproj + agg re-zero ----------
template <bool FIRST, bool PROJ>
__global__ void __launch_bounds__(256, 2)
k_fused(const float* __restrict__ BWh, const float* __restrict__ BWih,
        const float* __restrict__ BWhh, const float* __restrict__ BWs,
        const float* __restrict__ bih, const float* __restrict__ bhh) {
    __shared__ float As[32][68];
    __shared__ float Xs[32][68];
    __shared__ float Ss[32][68];
    int t = threadIdx.x;
    int warp = t >> 5, lane = t & 31;
    int wr = warp >> 2, wc = warp & 3;
    int tg = lane >> 2, tig = lane & 3;
    int m0 = blockIdx.x * 32;

#pragma unroll
    for (int p = 0; p < 2; p++) {
        int idx = t + p * 256;
        int r = idx >> 4, c4 = idx & 15;
        float4 v = *((const float4*)(g_agg + (size_t)(m0 + r) * 64) + c4);
        As[r][c4 * 4 + 0] = tf(v.x);
        As[r][c4 * 4 + 1] = tf(v.y);
        As[r][c4 * 4 + 2] = tf(v.z);
        As[r][c4 * 4 + 3] = tf(v.w);
        if (!FIRST) {
            float4 s = *((const float4*)(g_state + (size_t)(m0 + r) * 64) + c4);
            Ss[r][c4 * 4 + 0] = tf(s.x);
            Ss[r][c4 * 4 + 1] = tf(s.y);
            Ss[r][c4 * 4 + 2] = tf(s.z);
            Ss[r][c4 * 4 + 3] = tf(s.w);
        }
    }
    __syncthreads();

    // --- X = relu(agg @ Wh^T) ---
    {
        float accx[2][4] = {};
#pragma unroll
        for (int ks = 0; ks < 8; ks++) {
            int k0 = ks * 8;
            unsigned a0 = __float_as_uint(As[wr * 16 + tg][k0 + tig]);
            unsigned a1 = __float_as_uint(As[wr * 16 + tg + 8][k0 + tig]);
            unsigned a2 = __float_as_uint(As[wr * 16 + tg][k0 + tig + 4]);
            unsigned a3 = __float_as_uint(As[wr * 16 + tg + 8][k0 + tig + 4]);
#pragma unroll
            for (int cg = 0; cg < 2; cg++) {
                int ntg = wc * 2 + cg;
                float2 b = *(const float2*)(BWh + (((size_t)ks * 8 + ntg) * 32 + lane) * 2);
                mma8(accx[cg], a0, a1, a2, a3, __float_as_uint(b.x), __float_as_uint(b.y));
            }
        }
        __syncthreads();
        int rl = wr * 16 + tg;
#pragma unroll
        for (int cg = 0; cg < 2; cg++) {
            int col = (wc * 2 + cg) * 8 + 2 * tig;
            Xs[rl][col]         = tf(fmaxf(accx[cg][0], 0.f));
            Xs[rl][col + 1]     = tf(fmaxf(accx[cg][1], 0.f));
            Xs[rl + 8][col]     = tf(fmaxf(accx[cg][2], 0.f));
            Xs[rl + 8][col + 1] = tf(fmaxf(accx[cg][3], 0.f));
        }
        __syncthreads();
    }

    // --- gates ---
    float acc_r[2][4] = {}, acc_z[2][4] = {}, acc_ni[2][4] = {}, acc_nh[2][4] = {};
#pragma unroll
    for (int ks = 0; ks < 8; ks++) {
        int k0 = ks * 8;
        unsigned x0 = __float_as_uint(Xs[wr * 16 + tg][k0 + tig]);
        unsigned x1 = __float_as_uint(Xs[wr * 16 + tg + 8][k0 + tig]);
        unsigned x2 = __float_as_uint(Xs[wr * 16 + tg][k0 + tig + 4]);
        unsigned x3 = __float_as_uint(Xs[wr * 16 + tg + 8][k0 + tig + 4]);
        unsigned s0 = 0, s1 = 0, s2 = 0, s3 = 0;
        if (!FIRST) {
            s0 = __float_as_uint(Ss[wr * 16 + tg][k0 + tig]);
            s1 = __float_as_uint(Ss[wr * 16 + tg + 8][k0 + tig]);
            s2 = __float_as_uint(Ss[wr * 16 + tg][k0 + tig + 4]);
            s3 = __float_as_uint(Ss[wr * 16 + tg + 8][k0 + tig + 4]);
        }
#pragma unroll
        for (int cg = 0; cg < 2; cg++) {
            int nb = wc * 2 + cg;
#pragma unroll
            for (int g = 0; g < 3; g++) {
                int ntg = g * 8 + nb;
                float2 bi = *(const float2*)(BWih + (((size_t)ks * 24 + ntg) * 32 + lane) * 2);
                float* acc = (g == 0) ? acc_r[cg] : (g == 1) ? acc_z[cg] : acc_ni[cg];
                mma8(acc, x0, x1, x2, x3, __float_as_uint(bi.x), __float_as_uint(bi.y));
                if (!FIRST) {
                    float2 bh = *(const float2*)(BWhh + (((size_t)ks * 24 + ntg) * 32 + lane) * 2);
                    float* acch = (g == 0) ? acc_r[cg] : (g == 1) ? acc_z[cg] : acc_nh[cg];
                    mma8(acch, s0, s1, s2, s3, __float_as_uint(bh.x), __float_as_uint(bh.y));
                }
            }
        }
    }

    if (PROJ) __syncthreads();  // all gate-mma reads of Ss done before overwrite

    // --- GRU epilogue (+ stash new state tf32 in Ss when PROJ) ---
    int r0 = m0 + wr * 16 + tg;
#pragma unroll
    for (int cg = 0; cg < 2; cg++) {
        int col = (wc * 2 + cg) * 8 + 2 * tig;
        float2 bi_r = __ldg((const float2*)(bih + col));
        float2 bh_r = __ldg((const float2*)(bhh + col));
        float2 bi_z = __ldg((const float2*)(bih + 64 + col));
        float2 bh_z = __ldg((const float2*)(bhh + 64 + col));
        float2 bi_n = __ldg((const float2*)(bih + 128 + col));
        float2 bh_n = __ldg((const float2*)(bhh + 128 + col));
        float2 h0v = make_float2(0.f, 0.f), h1v = make_float2(0.f, 0.f);
        if (!FIRST) {
            h0v = *(const float2*)(g_state + (size_t)r0 * 64 + col);
            h1v = *(const float2*)(g_state + (size_t)(r0 + 8) * 64 + col);
        }
#define GRU1(ai, bx, hy, outv)                                                  \
        {                                                                       \
            float rr = sigf(acc_r[cg][ai] + bi_r.bx + bh_r.bx);                 \
            float zz = sigf(acc_z[cg][ai] + bi_z.bx + bh_z.bx);                 \
            float nn = tanhf(acc_ni[cg][ai] + bi_n.bx +                         \
                             rr * (acc_nh[cg][ai] + bh_n.bx));                  \
            outv = (1.f - zz) * nn + zz * hy;                                   \
        }
        float2 o0, o1;
        GRU1(0, x, h0v.x, o0.x)
        GRU1(1, y, h0v.y, o0.y)
        GRU1(2, x, h1v.x, o1.x)
        GRU1(3, y, h1v.y, o1.y)
#undef GRU1
        *(float2*)(g_state + (size_t)r0 * 64 + col) = o0;
        *(float2*)(g_state + (size_t)(r0 + 8) * 64 + col) = o1;
        if (PROJ) {
            int rl = wr * 16 + tg;
            Ss[rl][col] = tf(o0.x);
            Ss[rl][col + 1] = tf(o0.y);
            Ss[rl + 8][col] = tf(o1.x);
            Ss[rl + 8][col + 1] = tf(o1.y);
        }
    }

    if (PROJ) {
        __syncthreads();
        if (warp < 2) {
            // nproj = newstate @ Ws(next)^T : 32 rows x 8 cols
            float acc[4] = {};
#pragma unroll
            for (int ks = 0; ks < 8; ks++) {
                int k0 = ks * 8;
                unsigned a0 = __float_as_uint(Ss[warp * 16 + tg][k0 + tig]);
                unsigned a1 = __float_as_uint(Ss[warp * 16 + tg + 8][k0 + tig]);
                unsigned a2 = __float_as_uint(Ss[warp * 16 + tg][k0 + tig + 4]);
                unsigned a3 = __float_as_uint(Ss[warp * 16 + tg + 8][k0 + tig + 4]);
                float2 b = *(const float2*)(BWs + ((size_t)ks * 32 + lane) * 2);
                mma8(acc, a0, a1, a2, a3, __float_as_uint(b.x), __float_as_uint(b.y));
            }
            int row = m0 + warp * 16 + tg;
            *(float2*)(g_nproj + row * 8 + 2 * tig) = make_float2(acc[0], acc[1]);
            *(float2*)(g_nproj + (row + 8) * 8 + 2 * tig) = make_float2(acc[2], acc[3]);
        } else {
            // zero this block's agg slice for the next layer's edge kernel
            float4* a4 = (float4*)(g_agg + (size_t)m0 * 64);
            float4 z = make_float4(0.f, 0.f, 0.f, 0.f);
            for (int i = t - 64; i < 512; i += 192) a4[i] = z;
        }
    }
}

// ---------------- final score + deterministic scatter ----------------
__global__ void k_score(const float* __restrict__ wf, const int* __restrict__ nq,
                        const int* __restrict__ ne) {
    int w = (blockIdx.x * blockDim.x + threadIdx.x) >> 5;
    int lane = threadIdx.x & 31;
    if (w >= NNODE) return;
    float2 s2 = ((const float2*)(g_state + (size_t)w * 64))[lane];
    float2 w2 = __ldg((const float2*)wf + lane);
    float p = s2.x * w2.x + s2.y * w2.y;
#pragma unroll
    for (int m = 16; m >= 1; m >>= 1) p += __shfl_xor_sync(0xffffffffu, p, m);
    if (lane == 0) {
        g_scores[w] = p;
        int slot = __ldg(nq + w) * ENTC + __ldg(ne + w);
        atomicMax(&g_winner[slot], w);
    }
}
__global__ void k_scatter(const int* __restrict__ nq, const int* __restrict__ ne,
                          float* __restrict__ out) {
    int n = blockIdx.x * blockDim.x + threadIdx.x;
    if (n >= NNODE) return;
    int slot = __ldg(nq + n) * ENTC + __ldg(ne + n);
    if (g_winner[slot] == n) out[slot] = g_scores[n];
}

// ---------------- host launch ----------------
extern "C" void kernel_launch(void* const* d_in, const int* in_sizes, int n_in,
                              void* d_out, int out_size) {
    const int* relation = (const int*)d_in[0];
    const int* r_idx    = (const int*)d_in[1];
    const int* rel      = (const int*)d_in[2];
    const int* sub      = (const int*)d_in[3];
    const int* obj      = (const int*)d_in[4];
    const int* nq       = (const int*)d_in[6];
    const int* ne       = (const int*)d_in[7];
    const float* rela   = (const float*)d_in[8];
    const float* Ws     = (const float*)d_in[9];
    const float* Wr     = (const float*)d_in[10];
    const float* Wqr    = (const float*)d_in[11];
    const float* Wqrb   = (const float*)d_in[12];
    const float* wal    = (const float*)d_in[13];
    const float* walb   = (const float*)d_in[14];
    const float* Wh     = (const float*)d_in[15];
    const float* Wih    = (const float*)d_in[16];
    const float* Whh    = (const float*)d_in[17];
    const float* bih    = (const float*)d_in[18];
    const float* bhh    = (const float*)d_in[19];
    const float* Wfin   = (const float*)d_in[20];
    float* out = (float*)d_out;

    float *p_bWh, *p_bWih, *p_bWhh, *p_bWs, *p_rproj, *p_qproj;
    cudaGetSymbolAddress((void**)&p_bWh, g_bWh);
    cudaGetSymbolAddress((void**)&p_bWih, g_bWih);
    cudaGetSymbolAddress((void**)&p_bWhh, g_bWhh);
    cudaGetSymbolAddress((void**)&p_bWs, g_bWs);
    cudaGetSymbolAddress((void**)&p_rproj, g_rproj);
    cudaGetSymbolAddress((void**)&p_qproj, g_qproj);

    const int TB = 256;
    {
        int NS = NNODE * 16, NO = QNUM * ENTC / 4;
        int NI = NS > NO ? NS : NO;
        k_init<<<(NI + TB - 1) / TB, TB>>>((float4*)out);
    }
    k_bfrag<<<150, TB>>>(Wh, Wih, Whh, Ws);
    {
        int W = LNUM * (NR2C + QNUM);
        k_projRQ<<<(W * 32 + TB - 1) / TB, TB>>>(rela, Wr, Wqr, Wqrb, relation);
    }
    k_alpha0<<<(QNUM * NR2C + TB - 1) / TB, TB>>>(wal, walb);

    const int EG = ENUM * 16 / TB;  // 62500 blocks, exact
    for (int i = 0; i < LNUM; i++) {
        const float* emb = rela + (size_t)i * NR2C * DDIM;
        const float* rp = p_rproj + i * NR2C * ADIM;
        const float* qp = p_qproj + i * QNUM * ADIM;
        if (i == 0) {
            k_edge<false><<<EG, TB>>>(sub, rel, r_idx, obj, emb, wal, walb, rp, qp);
            k_fused<true, true><<<NNODE / 32, TB>>>(p_bWh, p_bWih, p_bWhh,
                                                    p_bWs + 512, bih, bhh);
        } else {
            k_edge<true><<<EG, TB>>>(
                sub + (size_t)i * ENUM, rel + (size_t)i * ENUM, r_idx + (size_t)i * ENUM,
                obj + (size_t)i * ENUM, emb, wal + i * 8, walb + i, rp, qp);
            if (i + 1 < LNUM)
                k_fused<false, true><<<NNODE / 32, TB>>>(p_bWh + i * 4096, p_bWih, p_bWhh,
                                                         p_bWs + (i + 1) * 512, bih, bhh);
            else
                k_fused<false, false><<<NNODE / 32, TB>>>(p_bWh + i * 4096, p_bWih, p_bWhh,
                                                          p_bWs, bih, bhh);
        }
    }

    k_score<<<(NNODE * 32 + TB - 1) / TB, TB>>>(Wfin, nq, ne);
    k_scatter<<<(NNODE + TB - 1) / TB, TB>>>(nq, ne, out);
}

// round 8
// speedup vs baseline: 1.4971x; 1.0239x over previous
#include <cuda_runtime.h>

#define LNUM 3
#define ENUM 1000000
#define NNODE 100000
#define DDIM 64
#define ADIM 8
#define NR2C 461
#define QNUM 1000
#define ENTC 10000

// ---------------- scratch (device globals; no allocation) ----------------
__device__ float g_state[NNODE * DDIM];
__device__ float g_agg[NNODE * DDIM];      // zero at load; re-zeroed by k_fused each layer
__device__ float g_nproj[NNODE * ADIM];
__device__ float g_rproj[LNUM * NR2C * ADIM];
__device__ float g_qproj[LNUM * QNUM * ADIM];
__device__ float g_alpha0[QNUM * NR2C];
__device__ float g_bWh[LNUM * 4096];
__device__ float g_bWih[12288];
__device__ float g_bWhh[12288];
__device__ float g_bWs[LNUM * 512];
__device__ float g_scores[NNODE];
__device__ int   g_winner[QNUM * ENTC];    // zero at load; k_clean restores per replay

// ---------------- helpers ----------------
__device__ __forceinline__ unsigned f2tf(float x) {
    unsigned u;
    asm("cvt.rna.tf32.f32 %0, %1;" : "=r"(u) : "f"(x));
    return u;
}
__device__ __forceinline__ float tf(float x) { return __uint_as_float(f2tf(x)); }
__device__ __forceinline__ float sigf(float x) { return 1.f / (1.f + __expf(-x)); }

__device__ __forceinline__ void mma8(float acc[4], unsigned a0, unsigned a1,
                                     unsigned a2, unsigned a3, unsigned b0, unsigned b1) {
    asm volatile(
        "mma.sync.aligned.m16n8k8.row.col.f32.tf32.tf32.f32 "
        "{%0,%1,%2,%3}, {%4,%5,%6,%7}, {%8,%9}, {%0,%1,%2,%3};"
        : "+f"(acc[0]), "+f"(acc[1]), "+f"(acc[2]), "+f"(acc[3])
        : "r"(a0), "r"(a1), "r"(a2), "r"(a3), "r"(b0), "r"(b1));
}

// ---------------- init: only the output needs zeroing ----------------
__global__ void k_init(float4* out4) {
    int i = blockIdx.x * blockDim.x + threadIdx.x;
    if (i < QNUM * ENTC / 4) out4[i] = make_float4(0.f, 0.f, 0.f, 0.f);
}

// ---------------- B-fragment precompute (tf32, mma-swizzled) ----------------
__device__ __forceinline__ float bval(const float* W, int e, int NT) {
    int j = e & 1;
    int lane = (e >> 1) & 31;
    int nk = e >> 6;
    int ntg = nk % NT;
    int ks = nk / NT;
    int n = ntg * 8 + (lane >> 2);
    int k = ks * 8 + (lane & 3) + 4 * j;
    return __uint_as_float(f2tf(W[n * 64 + k]));
}
__global__ void k_bfrag(const float* __restrict__ Wh, const float* __restrict__ Wih,
                        const float* __restrict__ Whh, const float* __restrict__ Ws) {
    int i = blockIdx.x * blockDim.x + threadIdx.x;
    const int WH = 4096, WI = 12288, WS = 512;
    if (i < 3 * WH) {
        int layer = i / WH, e = i % WH;
        g_bWh[i] = bval(Wh + layer * 4096, e, 8);
    } else if (i < 3 * WH + WI) {
        int e = i - 3 * WH;
        g_bWih[e] = bval(Wih, e, 24);
    } else if (i < 3 * WH + 2 * WI) {
        int e = i - 3 * WH - WI;
        g_bWhh[e] = bval(Whh, e, 24);
    } else if (i < 3 * WH + 2 * WI + 3 * WS) {
        int e = i - 3 * WH - 2 * WI;
        int layer = e / WS, ee = e % WS;
        g_bWs[e] = bval(Ws + layer * 512, ee, 1);
    }
}

// ---------------- rel/query projections for ALL layers (state-independent) ---
__global__ void k_projRQ(const float* __restrict__ rela, const float* __restrict__ Wr,
                         const float* __restrict__ Wqr, const float* __restrict__ Wqrb,
                         const int* __restrict__ relation) {
    int w = (blockIdx.x * blockDim.x + threadIdx.x) >> 5;
    int lane = threadIdx.x & 31;
    const int PER = NR2C + QNUM;
    if (w >= LNUM * PER) return;
    int layer = w / PER;
    int r = w % PER;
    const float* emb = rela + (size_t)layer * NR2C * DDIM;
    const float* src;
    const float* W;
    float* dst;
    bool isQ;
    if (r < NR2C) {
        src = emb + (size_t)r * 64; W = Wr + layer * 512;
        dst = g_rproj + (layer * NR2C + r) * 8; isQ = false;
    } else {
        int q = r - NR2C;
        src = emb + (size_t)__ldg(relation + q) * 64; W = Wqr + layer * 512;
        dst = g_qproj + (layer * QNUM + q) * 8; isQ = true;
    }
    float2 s2 = ((const float2*)src)[lane];
    float res = 0.f;
#pragma unroll
    for (int a = 0; a < 8; a++) {
        float2 w2 = __ldg((const float2*)(W + a * 64) + lane);
        float p = s2.x * w2.x + s2.y * w2.y;
#pragma unroll
        for (int m = 16; m >= 1; m >>= 1) p += __shfl_xor_sync(0xffffffffu, p, m);
        if (lane == a) res = p;
    }
    if (lane < 8) dst[lane] = res + (isQ ? __ldg(Wqrb + layer * 8 + lane) : 0.f);
}

// ---------------- layer-0 alpha table (vectorized) ---------------------------
__global__ void k_alpha0(const float* __restrict__ wal, const float* __restrict__ walb) {
    int i = blockIdx.x * blockDim.x + threadIdx.x;
    if (i >= QNUM * NR2C) return;
    int q = i / NR2C, r = i % NR2C;
    float4 r0 = __ldg((const float4*)(g_rproj + r * 8));
    float4 r1 = __ldg((const float4*)(g_rproj + r * 8) + 1);
    float4 q0 = __ldg((const float4*)(g_qproj + q * 8));
    float4 q1 = __ldg((const float4*)(g_qproj + q * 8) + 1);
    float4 w0 = __ldg((const float4*)wal);
    float4 w1 = __ldg((const float4*)wal + 1);
    float p = fmaxf(r0.x + q0.x, 0.f) * w0.x + fmaxf(r0.y + q0.y, 0.f) * w0.y
            + fmaxf(r0.z + q0.z, 0.f) * w0.z + fmaxf(r0.w + q0.w, 0.f) * w0.w
            + fmaxf(r1.x + q1.x, 0.f) * w1.x + fmaxf(r1.y + q1.y, 0.f) * w1.y
            + fmaxf(r1.z + q1.z, 0.f) * w1.z + fmaxf(r1.w + q1.w, 0.f) * w1.w;
    g_alpha0[i] = sigf(p + __ldg(walb));
}

// ---------------- edge kernel: 16 lanes/edge, full-row coalesced -------------
template <bool HS>
__global__ void k_edge(const int* __restrict__ sub, const int* __restrict__ rel,
                       const int* __restrict__ ridx, const int* __restrict__ obj,
                       const float* __restrict__ emb, const float* __restrict__ wal,
                       const float* __restrict__ walb, const float* __restrict__ rproj,
                       const float* __restrict__ qproj) {
    int gt = blockIdx.x * blockDim.x + threadIdx.x;
    int e = gt >> 4;
    int sl = threadIdx.x & 15;
    int r = __ldg(rel + e);
    int o = __ldg(obj + e);
    int q = __ldg(ridx + e);

    if (HS) {
        int s = __ldg(sub + e);
        float p = 0.f;
        if (sl < 8) {
            float t = __ldg(rproj + r * 8 + sl) + __ldg(qproj + q * 8 + sl)
                    + g_nproj[s * 8 + sl];
            p = fmaxf(t, 0.f) * __ldg(wal + sl);
        }
        p += __shfl_xor_sync(0xffffffffu, p, 1);
        p += __shfl_xor_sync(0xffffffffu, p, 2);
        p += __shfl_xor_sync(0xffffffffu, p, 4);
        p += __shfl_xor_sync(0xffffffffu, p, 8);
        float alpha = sigf(p + __ldg(walb));

        float4 hr = __ldg((const float4*)emb + r * 16 + sl);
        float4 hs = __ldg((const float4*)g_state + (size_t)s * 16 + sl);
        asm volatile("red.global.add.v4.f32 [%0], {%1,%2,%3,%4};"
                     :: "l"(g_agg + (size_t)o * 64 + sl * 4),
                        "f"(alpha * (hs.x + hr.x)), "f"(alpha * (hs.y + hr.y)),
                        "f"(alpha * (hs.z + hr.z)), "f"(alpha * (hs.w + hr.w))
                     : "memory");
    } else {
        float alpha = __ldg(g_alpha0 + q * NR2C + r);
        float4 hr = __ldg((const float4*)emb + r * 16 + sl);
        asm volatile("red.global.add.v4.f32 [%0], {%1,%2,%3,%4};"
                     :: "l"(g_agg + (size_t)o * 64 + sl * 4),
                        "f"(alpha * hr.x), "f"(alpha * hr.y),
                        "f"(alpha * hr.z), "f"(alpha * hr.w) : "memory");
    }
}

// ---------------- fused node phase (+nproj, +score, always re-zero agg) ------
template <bool FIRST, bool PROJ, bool SCORE>
__global__ void __launch_bounds__(256, 2)
k_fused(const float* __restrict__ BWh, const float* __restrict__ BWih,
        const float* __restrict__ BWhh, const float* __restrict__ BWs,
        const float* __restrict__ bih, const float* __restrict__ bhh,
        const float* __restrict__ wf, const int* __restrict__ nq,
        const int* __restrict__ ne) {
    __shared__ float As[32][68];
    __shared__ float Xs[32][68];
    __shared__ float Ss[32][68];
    __shared__ float sbuf[32];
    int t = threadIdx.x;
    int warp = t >> 5, lane = t & 31;
    int wr = warp >> 2, wc = warp & 3;
    int tg = lane >> 2, tig = lane & 3;
    int m0 = blockIdx.x * 32;

    if (SCORE && t < 32) sbuf[t] = 0.f;

#pragma unroll
    for (int p = 0; p < 2; p++) {
        int idx = t + p * 256;
        int r = idx >> 4, c4 = idx & 15;
        float4 v = *((const float4*)(g_agg + (size_t)(m0 + r) * 64) + c4);
        As[r][c4 * 4 + 0] = tf(v.x);
        As[r][c4 * 4 + 1] = tf(v.y);
        As[r][c4 * 4 + 2] = tf(v.z);
        As[r][c4 * 4 + 3] = tf(v.w);
        if (!FIRST) {
            float4 s = *((const float4*)(g_state + (size_t)(m0 + r) * 64) + c4);
            Ss[r][c4 * 4 + 0] = tf(s.x);
            Ss[r][c4 * 4 + 1] = tf(s.y);
            Ss[r][c4 * 4 + 2] = tf(s.z);
            Ss[r][c4 * 4 + 3] = tf(s.w);
        }
    }
    __syncthreads();

    // zero this block's agg slice for the next layer / next replay
    {
        float4* a4 = (float4*)(g_agg + (size_t)m0 * 64);
        float4 z = make_float4(0.f, 0.f, 0.f, 0.f);
        a4[t] = z;
        a4[t + 256] = z;
    }

    // --- X = relu(agg @ Wh^T) ---
    {
        float accx[2][4] = {};
#pragma unroll
        for (int ks = 0; ks < 8; ks++) {
            int k0 = ks * 8;
            unsigned a0 = __float_as_uint(As[wr * 16 + tg][k0 + tig]);
            unsigned a1 = __float_as_uint(As[wr * 16 + tg + 8][k0 + tig]);
            unsigned a2 = __float_as_uint(As[wr * 16 + tg][k0 + tig + 4]);
            unsigned a3 = __float_as_uint(As[wr * 16 + tg + 8][k0 + tig + 4]);
#pragma unroll
            for (int cg = 0; cg < 2; cg++) {
                int ntg = wc * 2 + cg;
                float2 b = *(const float2*)(BWh + (((size_t)ks * 8 + ntg) * 32 + lane) * 2);
                mma8(accx[cg], a0, a1, a2, a3, __float_as_uint(b.x), __float_as_uint(b.y));
            }
        }
        __syncthreads();
        int rl = wr * 16 + tg;
#pragma unroll
        for (int cg = 0; cg < 2; cg++) {
            int col = (wc * 2 + cg) * 8 + 2 * tig;
            Xs[rl][col]         = tf(fmaxf(accx[cg][0], 0.f));
            Xs[rl][col + 1]     = tf(fmaxf(accx[cg][1], 0.f));
            Xs[rl + 8][col]     = tf(fmaxf(accx[cg][2], 0.f));
            Xs[rl + 8][col + 1] = tf(fmaxf(accx[cg][3], 0.f));
        }
        __syncthreads();
    }

    // --- gates ---
    float acc_r[2][4] = {}, acc_z[2][4] = {}, acc_ni[2][4] = {}, acc_nh[2][4] = {};
#pragma unroll
    for (int ks = 0; ks < 8; ks++) {
        int k0 = ks * 8;
        unsigned x0 = __float_as_uint(Xs[wr * 16 + tg][k0 + tig]);
        unsigned x1 = __float_as_uint(Xs[wr * 16 + tg + 8][k0 + tig]);
        unsigned x2 = __float_as_uint(Xs[wr * 16 + tg][k0 + tig + 4]);
        unsigned x3 = __float_as_uint(Xs[wr * 16 + tg + 8][k0 + tig + 4]);
        unsigned s0 = 0, s1 = 0, s2 = 0, s3 = 0;
        if (!FIRST) {
            s0 = __float_as_uint(Ss[wr * 16 + tg][k0 + tig]);
            s1 = __float_as_uint(Ss[wr * 16 + tg + 8][k0 + tig]);
            s2 = __float_as_uint(Ss[wr * 16 + tg][k0 + tig + 4]);
            s3 = __float_as_uint(Ss[wr * 16 + tg + 8][k0 + tig + 4]);
        }
#pragma unroll
        for (int cg = 0; cg < 2; cg++) {
            int nb = wc * 2 + cg;
#pragma unroll
            for (int g = 0; g < 3; g++) {
                int ntg = g * 8 + nb;
                float2 bi = *(const float2*)(BWih + (((size_t)ks * 24 + ntg) * 32 + lane) * 2);
                float* acc = (g == 0) ? acc_r[cg] : (g == 1) ? acc_z[cg] : acc_ni[cg];
                mma8(acc, x0, x1, x2, x3, __float_as_uint(bi.x), __float_as_uint(bi.y));
                if (!FIRST) {
                    float2 bh = *(const float2*)(BWhh + (((size_t)ks * 24 + ntg) * 32 + lane) * 2);
                    float* acch = (g == 0) ? acc_r[cg] : (g == 1) ? acc_z[cg] : acc_nh[cg];
                    mma8(acch, s0, s1, s2, s3, __float_as_uint(bh.x), __float_as_uint(bh.y));
                }
            }
        }
    }

    if (PROJ) __syncthreads();  // all gate-mma reads of Ss done before overwrite

    // --- GRU epilogue ---
    int r0 = m0 + wr * 16 + tg;
    float ps0 = 0.f, ps1 = 0.f;
#pragma unroll
    for (int cg = 0; cg < 2; cg++) {
        int col = (wc * 2 + cg) * 8 + 2 * tig;
        float2 bi_r = __ldg((const float2*)(bih + col));
        float2 bh_r = __ldg((const float2*)(bhh + col));
        float2 bi_z = __ldg((const float2*)(bih + 64 + col));
        float2 bh_z = __ldg((const float2*)(bhh + 64 + col));
        float2 bi_n = __ldg((const float2*)(bih + 128 + col));
        float2 bh_n = __ldg((const float2*)(bhh + 128 + col));
        float2 h0v = make_float2(0.f, 0.f), h1v = make_float2(0.f, 0.f);
        if (!FIRST) {
            h0v = *(const float2*)(g_state + (size_t)r0 * 64 + col);
            h1v = *(const float2*)(g_state + (size_t)(r0 + 8) * 64 + col);
        }
#define GRU1(ai, bx, hy, outv)                                                  \
        {                                                                       \
            float rr = sigf(acc_r[cg][ai] + bi_r.bx + bh_r.bx);                 \
            float zz = sigf(acc_z[cg][ai] + bi_z.bx + bh_z.bx);                 \
            float nn = tanhf(acc_ni[cg][ai] + bi_n.bx +                         \
                             rr * (acc_nh[cg][ai] + bh_n.bx));                  \
            outv = (1.f - zz) * nn + zz * hy;                                   \
        }
        float2 o0, o1;
        GRU1(0, x, h0v.x, o0.x)
        GRU1(1, y, h0v.y, o0.y)
        GRU1(2, x, h1v.x, o1.x)
        GRU1(3, y, h1v.y, o1.y)
#undef GRU1
        *(float2*)(g_state + (size_t)r0 * 64 + col) = o0;
        *(float2*)(g_state + (size_t)(r0 + 8) * 64 + col) = o1;
        if (PROJ) {
            int rl = wr * 16 + tg;
            Ss[rl][col] = tf(o0.x);
            Ss[rl][col + 1] = tf(o0.y);
            Ss[rl + 8][col] = tf(o1.x);
            Ss[rl + 8][col + 1] = tf(o1.y);
        }
        if (SCORE) {
            float wfa = __ldg(wf + col), wfb = __ldg(wf + col + 1);
            ps0 += o0.x * wfa + o0.y * wfb;
            ps1 += o1.x * wfa + o1.y * wfb;
        }
    }

    if (PROJ) {
        __syncthreads();
        if (warp < 2) {
            float acc[4] = {};
#pragma unroll
            for (int ks = 0; ks < 8; ks++) {
                int k0 = ks * 8;
                unsigned a0 = __float_as_uint(Ss[warp * 16 + tg][k0 + tig]);
                unsigned a1 = __float_as_uint(Ss[warp * 16 + tg + 8][k0 + tig]);
                unsigned a2 = __float_as_uint(Ss[warp * 16 + tg][k0 + tig + 4]);
                unsigned a3 = __float_as_uint(Ss[warp * 16 + tg + 8][k0 + tig + 4]);
                float2 b = *(const float2*)(BWs + ((size_t)ks * 32 + lane) * 2);
                mma8(acc, a0, a1, a2, a3, __float_as_uint(b.x), __float_as_uint(b.y));
            }
            int row = m0 + warp * 16 + tg;
            *(float2*)(g_nproj + row * 8 + 2 * tig) = make_float2(acc[0], acc[1]);
            *(float2*)(g_nproj + (row + 8) * 8 + 2 * tig) = make_float2(acc[2], acc[3]);
        }
    }

    if (SCORE) {
        int rl = wr * 16 + tg;
        atomicAdd(&sbuf[rl], ps0);
        atomicAdd(&sbuf[rl + 8], ps1);
        __syncthreads();
        if (t < 32) {
            int row = m0 + t;
            float s = sbuf[t];
            g_scores[row] = s;
            int slot = __ldg(nq + row) * ENTC + __ldg(ne + row);
            atomicMax(&g_winner[slot], row);
        }
    }
}

// ---------------- scatter + winner cleanup ----------------
__global__ void k_scatter(const int* __restrict__ nq, const int* __restrict__ ne,
                          float* __restrict__ out) {
    int n = blockIdx.x * blockDim.x + threadIdx.x;
    if (n >= NNODE) return;
    int slot = __ldg(nq + n) * ENTC + __ldg(ne + n);
    if (g_winner[slot] == n) out[slot] = g_scores[n];
}
__global__ void k_clean(const int* __restrict__ nq, const int* __restrict__ ne) {
    int n = blockIdx.x * blockDim.x + threadIdx.x;
    if (n >= NNODE) return;
    g_winner[__ldg(nq + n) * ENTC + __ldg(ne + n)] = 0;
}

// ---------------- host launch ----------------
extern "C" void kernel_launch(void* const* d_in, const int* in_sizes, int n_in,
                              void* d_out, int out_size) {
    const int* relation = (const int*)d_in[0];
    const int* r_idx    = (const int*)d_in[1];
    const int* rel      = (const int*)d_in[2];
    const int* sub      = (const int*)d_in[3];
    const int* obj      = (const int*)d_in[4];
    const int* nq       = (const int*)d_in[6];
    const int* ne       = (const int*)d_in[7];
    const float* rela   = (const float*)d_in[8];
    const float* Ws     = (const float*)d_in[9];
    const float* Wr     = (const float*)d_in[10];
    const float* Wqr    = (const float*)d_in[11];
    const float* Wqrb   = (const float*)d_in[12];
    const float* wal    = (const float*)d_in[13];
    const float* walb   = (const float*)d_in[14];
    const float* Wh     = (const float*)d_in[15];
    const float* Wih    = (const float*)d_in[16];
    const float* Whh    = (const float*)d_in[17];
    const float* bih    = (const float*)d_in[18];
    const float* bhh    = (const float*)d_in[19];
    const float* Wfin   = (const float*)d_in[20];
    float* out = (float*)d_out;

    float *p_bWh, *p_bWih, *p_bWhh, *p_bWs, *p_rproj, *p_qproj;
    cudaGetSymbolAddress((void**)&p_bWh, g_bWh);
    cudaGetSymbolAddress((void**)&p_bWih, g_bWih);
    cudaGetSymbolAddress((void**)&p_bWhh, g_bWhh);
    cudaGetSymbolAddress((void**)&p_bWs, g_bWs);
    cudaGetSymbolAddress((void**)&p_rproj, g_rproj);
    cudaGetSymbolAddress((void**)&p_qproj, g_qproj);

    const int TB = 256;
    k_init<<<(QNUM * ENTC / 4 + TB - 1) / TB, TB>>>((float4*)out);
    k_bfrag<<<150, TB>>>(Wh, Wih, Whh, Ws);
    {
        int W = LNUM * (NR2C + QNUM);
        k_projRQ<<<(W * 32 + TB - 1) / TB, TB>>>(rela, Wr, Wqr, Wqrb, relation);
    }
    k_alpha0<<<(QNUM * NR2C + TB - 1) / TB, TB>>>(wal, walb);

    const int EG = ENUM * 16 / TB;
    const int FG = NNODE / 32;
    for (int i = 0; i < LNUM; i++) {
        const float* emb = rela + (size_t)i * NR2C * DDIM;
        const float* rp = p_rproj + i * NR2C * ADIM;
        const float* qp = p_qproj + i * QNUM * ADIM;
        if (i == 0) {
            k_edge<false><<<EG, TB>>>(sub, rel, r_idx, obj, emb, wal, walb, rp, qp);
            k_fused<true, true, false><<<FG, TB>>>(p_bWh, p_bWih, p_bWhh,
                                                   p_bWs + 512, bih, bhh, Wfin, nq, ne);
        } else {
            k_edge<true><<<EG, TB>>>(
                sub + (size_t)i * ENUM, rel + (size_t)i * ENUM, r_idx + (size_t)i * ENUM,
                obj + (size_t)i * ENUM, emb, wal + i * 8, walb + i, rp, qp);
            if (i + 1 < LNUM)
                k_fused<false, true, false><<<FG, TB>>>(p_bWh + i * 4096, p_bWih, p_bWhh,
                                                        p_bWs + (i + 1) * 512, bih, bhh,
                                                        Wfin, nq, ne);
            else
                k_fused<false, false, true><<<FG, TB>>>(p_bWh + i * 4096, p_bWih, p_bWhh,
                                                        p_bWs, bih, bhh, Wfin, nq, ne);
        }
    }

    k_scatter<<<(NNODE + TB - 1) / TB, TB>>>(nq, ne, out);
    k_clean<<<(NNODE + TB - 1) / TB, TB>>>(nq, ne);
}